// round 1
// baseline (speedup 1.0000x reference)
#include <cuda_runtime.h>
#include <math.h>

#define EMBED 1024
#define NTOK  8192
#define BK    8
#define LDSS  132   // smem row stride (pad 128 -> 132 to kill transpose-store conflicts)

// Scratch (alloc-free rule: device globals)
__device__ float g_Q[(size_t)NTOK * EMBED];
__device__ float g_K[(size_t)NTOK * EMBED];
__device__ float g_S[(size_t)NTOK * NTOK];

// C[M,N] = scale * A[M,Kd] @ op(B);  TRANSB=0: B is [Kd,N]; TRANSB=1: B is [N,Kd] (C=A@B^T)
template<int TRANSB>
__global__ __launch_bounds__(256)
void sgemm128(const float* __restrict__ A, const float* __restrict__ B,
              float* __restrict__ C, int M, int N, int Kd, float scale)
{
    __shared__ float As[BK * LDSS];
    __shared__ float Bs[BK * LDSS];

    const int tid = threadIdx.x;
    const int bm = blockIdx.y * 128;
    const int bn = blockIdx.x * 128;
    const int tx = tid & 15;
    const int ty = tid >> 4;

    // A tile load: 128 rows x 8 k, one float4 per thread
    const int ar = tid >> 1;
    const int ak = (tid & 1) * 4;
    const float* Ap = A + (size_t)(bm + ar) * Kd + ak;

    const float* Bp;
    int br, bk;
    if (TRANSB) {            // B[N,Kd], load like A
        br = tid >> 1;        // 0..127 (n within tile)
        bk = (tid & 1) * 4;   // k offset
        Bp = B + (size_t)(bn + br) * Kd + bk;
    } else {                  // B[Kd,N]
        br = tid >> 5;        // k row 0..7
        bk = (tid & 31) * 4;  // n offset
        Bp = B + (size_t)br * N + (bn + bk);
    }

    float acc[8][8];
#pragma unroll
    for (int i = 0; i < 8; i++)
#pragma unroll
        for (int j = 0; j < 8; j++) acc[i][j] = 0.f;

    float4 areg = *(const float4*)Ap;
    float4 breg = *(const float4*)Bp;

    // prologue store
    As[(ak + 0) * LDSS + ar] = areg.x;
    As[(ak + 1) * LDSS + ar] = areg.y;
    As[(ak + 2) * LDSS + ar] = areg.z;
    As[(ak + 3) * LDSS + ar] = areg.w;
    if (TRANSB) {
        Bs[(bk + 0) * LDSS + br] = breg.x;
        Bs[(bk + 1) * LDSS + br] = breg.y;
        Bs[(bk + 2) * LDSS + br] = breg.z;
        Bs[(bk + 3) * LDSS + br] = breg.w;
    } else {
        *(float4*)&Bs[br * LDSS + bk] = breg;
    }

    const int ktiles = Kd / BK;
    for (int kt = 0; kt < ktiles; ++kt) {
        __syncthreads();
        if (kt + 1 < ktiles) {             // prefetch next tile into regs
            Ap += BK;
            areg = *(const float4*)Ap;
            if (TRANSB) Bp += BK; else Bp += (size_t)BK * N;
            breg = *(const float4*)Bp;
        }
#pragma unroll
        for (int kk = 0; kk < BK; ++kk) {
            float4 a0 = *(const float4*)&As[kk * LDSS + ty * 4];
            float4 a1 = *(const float4*)&As[kk * LDSS + 64 + ty * 4];
            float4 b0 = *(const float4*)&Bs[kk * LDSS + tx * 4];
            float4 b1 = *(const float4*)&Bs[kk * LDSS + 64 + tx * 4];
            float a[8] = {a0.x, a0.y, a0.z, a0.w, a1.x, a1.y, a1.z, a1.w};
            float b[8] = {b0.x, b0.y, b0.z, b0.w, b1.x, b1.y, b1.z, b1.w};
#pragma unroll
            for (int i = 0; i < 8; i++)
#pragma unroll
                for (int j = 0; j < 8; j++)
                    acc[i][j] = fmaf(a[i], b[j], acc[i][j]);
        }
        __syncthreads();
        if (kt + 1 < ktiles) {
            As[(ak + 0) * LDSS + ar] = areg.x;
            As[(ak + 1) * LDSS + ar] = areg.y;
            As[(ak + 2) * LDSS + ar] = areg.z;
            As[(ak + 3) * LDSS + ar] = areg.w;
            if (TRANSB) {
                Bs[(bk + 0) * LDSS + br] = breg.x;
                Bs[(bk + 1) * LDSS + br] = breg.y;
                Bs[(bk + 2) * LDSS + br] = breg.z;
                Bs[(bk + 3) * LDSS + br] = breg.w;
            } else {
                *(float4*)&Bs[br * LDSS + bk] = breg;
            }
        }
    }

#pragma unroll
    for (int i = 0; i < 8; i++) {
        int m = bm + ((i < 4) ? (ty * 4 + i) : (64 + ty * 4 + i - 4));
        float4 c0 = make_float4(acc[i][0] * scale, acc[i][1] * scale,
                                acc[i][2] * scale, acc[i][3] * scale);
        float4 c1 = make_float4(acc[i][4] * scale, acc[i][5] * scale,
                                acc[i][6] * scale, acc[i][7] * scale);
        *(float4*)&C[(size_t)m * N + bn + tx * 4] = c0;
        *(float4*)&C[(size_t)m * N + bn + 64 + tx * 4] = c1;
    }
}

// In-place row softmax over NTOK columns. One CTA (256 thr) per row; row held in regs.
__global__ __launch_bounds__(256)
void softmax8192(float* __restrict__ S)
{
    __shared__ float red[256];
    const int row = blockIdx.x;
    const int tid = threadIdx.x;
    float4* p = (float4*)(S + (size_t)row * NTOK);

    float4 v[8];
    float mx = -3.402823466e+38f;
#pragma unroll
    for (int i = 0; i < 8; i++) {
        v[i] = p[tid + i * 256];
        mx = fmaxf(mx, fmaxf(fmaxf(v[i].x, v[i].y), fmaxf(v[i].z, v[i].w)));
    }
    red[tid] = mx;
    __syncthreads();
    for (int s = 128; s > 0; s >>= 1) {
        if (tid < s) red[tid] = fmaxf(red[tid], red[tid + s]);
        __syncthreads();
    }
    mx = red[0];
    __syncthreads();

    float sum = 0.f;
#pragma unroll
    for (int i = 0; i < 8; i++) {
        v[i].x = expf(v[i].x - mx);
        v[i].y = expf(v[i].y - mx);
        v[i].z = expf(v[i].z - mx);
        v[i].w = expf(v[i].w - mx);
        sum += (v[i].x + v[i].y) + (v[i].z + v[i].w);
    }
    red[tid] = sum;
    __syncthreads();
    for (int s = 128; s > 0; s >>= 1) {
        if (tid < s) red[tid] += red[tid + s];
        __syncthreads();
    }
    const float inv = 1.f / red[0];

#pragma unroll
    for (int i = 0; i < 8; i++) {
        v[i].x *= inv; v[i].y *= inv; v[i].z *= inv; v[i].w *= inv;
        p[tid + i * 256] = v[i];
    }
}

extern "C" void kernel_launch(void* const* d_in, const int* in_sizes, int n_in,
                              void* d_out, int out_size)
{
    const float* Wr = (const float*)d_in[0];   // rotation_params [1024,1024]
    const float* We = (const float*)d_in[1];   // entangle_params [1024,1024]
    const float* X  = (const float*)d_in[2];   // inputs [8192,1024]
    float* out = (float*)d_out;                // [8192,1024] fp32

    float *Qp, *Kp, *Sp;
    cudaGetSymbolAddress((void**)&Qp, g_Q);
    cudaGetSymbolAddress((void**)&Kp, g_K);
    cudaGetSymbolAddress((void**)&Sp, g_S);

    dim3 blk(256);
    // Q = X @ Wr ; K = X @ We
    sgemm128<0><<<dim3(EMBED / 128, NTOK / 128), blk>>>(X, Wr, Qp, NTOK, EMBED, EMBED, 1.0f);
    sgemm128<0><<<dim3(EMBED / 128, NTOK / 128), blk>>>(X, We, Kp, NTOK, EMBED, EMBED, 1.0f);
    // S = (Q @ K^T) / 32
    sgemm128<1><<<dim3(NTOK / 128, NTOK / 128), blk>>>(Qp, Kp, Sp, NTOK, NTOK, EMBED, 0.03125f);
    // softmax rows in place
    softmax8192<<<NTOK, 256>>>(Sp);
    // O = P @ X
    sgemm128<0><<<dim3(EMBED / 128, NTOK / 128), blk>>>(Sp, X, out, NTOK, EMBED, NTOK, 1.0f);
}

// round 3
// speedup vs baseline: 1.8597x; 1.8597x over previous
#include <cuda_runtime.h>
#include <math.h>

#define EMBED 1024
#define NTOK  8192
#define BK    8
#define LDSS  132   // smem row stride (pad 128 -> 132 to kill transpose-store conflicts)
#define CAP   128   // max sparse candidates per row before dense fallback

// Scratch (alloc-free rule: device globals)
__device__ float g_Q[(size_t)NTOK * EMBED];
__device__ float g_K[(size_t)NTOK * EMBED];
__device__ float g_S[(size_t)NTOK * NTOK];

// C[M,N] = scale * A[M,Kd] @ op(B);  TRANSB=0: B is [Kd,N]; TRANSB=1: B is [N,Kd] (C=A@B^T)
template<int TRANSB>
__global__ __launch_bounds__(256)
void sgemm128(const float* __restrict__ A, const float* __restrict__ B,
              float* __restrict__ C, int M, int N, int Kd, float scale)
{
    __shared__ float As[BK * LDSS];
    __shared__ float Bs[BK * LDSS];

    const int tid = threadIdx.x;
    const int bm = blockIdx.y * 128;
    const int bn = blockIdx.x * 128;
    const int tx = tid & 15;
    const int ty = tid >> 4;

    const int ar = tid >> 1;
    const int ak = (tid & 1) * 4;
    const float* Ap = A + (size_t)(bm + ar) * Kd + ak;

    const float* Bp;
    int br, bk;
    if (TRANSB) {            // B[N,Kd], load like A
        br = tid >> 1;
        bk = (tid & 1) * 4;
        Bp = B + (size_t)(bn + br) * Kd + bk;
    } else {                  // B[Kd,N]
        br = tid >> 5;
        bk = (tid & 31) * 4;
        Bp = B + (size_t)br * N + (bn + bk);
    }

    float acc[8][8];
#pragma unroll
    for (int i = 0; i < 8; i++)
#pragma unroll
        for (int j = 0; j < 8; j++) acc[i][j] = 0.f;

    float4 areg = *(const float4*)Ap;
    float4 breg = *(const float4*)Bp;

    As[(ak + 0) * LDSS + ar] = areg.x;
    As[(ak + 1) * LDSS + ar] = areg.y;
    As[(ak + 2) * LDSS + ar] = areg.z;
    As[(ak + 3) * LDSS + ar] = areg.w;
    if (TRANSB) {
        Bs[(bk + 0) * LDSS + br] = breg.x;
        Bs[(bk + 1) * LDSS + br] = breg.y;
        Bs[(bk + 2) * LDSS + br] = breg.z;
        Bs[(bk + 3) * LDSS + br] = breg.w;
    } else {
        *(float4*)&Bs[br * LDSS + bk] = breg;
    }

    const int ktiles = Kd / BK;
    for (int kt = 0; kt < ktiles; ++kt) {
        __syncthreads();
        if (kt + 1 < ktiles) {
            Ap += BK;
            areg = *(const float4*)Ap;
            if (TRANSB) Bp += BK; else Bp += (size_t)BK * N;
            breg = *(const float4*)Bp;
        }
#pragma unroll
        for (int kk = 0; kk < BK; ++kk) {
            float4 a0 = *(const float4*)&As[kk * LDSS + ty * 4];
            float4 a1 = *(const float4*)&As[kk * LDSS + 64 + ty * 4];
            float4 b0 = *(const float4*)&Bs[kk * LDSS + tx * 4];
            float4 b1 = *(const float4*)&Bs[kk * LDSS + 64 + tx * 4];
            float a[8] = {a0.x, a0.y, a0.z, a0.w, a1.x, a1.y, a1.z, a1.w};
            float b[8] = {b0.x, b0.y, b0.z, b0.w, b1.x, b1.y, b1.z, b1.w};
#pragma unroll
            for (int i = 0; i < 8; i++)
#pragma unroll
                for (int j = 0; j < 8; j++)
                    acc[i][j] = fmaf(a[i], b[j], acc[i][j]);
        }
        __syncthreads();
        if (kt + 1 < ktiles) {
            As[(ak + 0) * LDSS + ar] = areg.x;
            As[(ak + 1) * LDSS + ar] = areg.y;
            As[(ak + 2) * LDSS + ar] = areg.z;
            As[(ak + 3) * LDSS + ar] = areg.w;
            if (TRANSB) {
                Bs[(bk + 0) * LDSS + br] = breg.x;
                Bs[(bk + 1) * LDSS + br] = breg.y;
                Bs[(bk + 2) * LDSS + br] = breg.z;
                Bs[(bk + 3) * LDSS + br] = breg.w;
            } else {
                *(float4*)&Bs[br * LDSS + bk] = breg;
            }
        }
    }

#pragma unroll
    for (int i = 0; i < 8; i++) {
        int m = bm + ((i < 4) ? (ty * 4 + i) : (64 + ty * 4 + i - 4));
        float4 c0 = make_float4(acc[i][0] * scale, acc[i][1] * scale,
                                acc[i][2] * scale, acc[i][3] * scale);
        float4 c1 = make_float4(acc[i][4] * scale, acc[i][5] * scale,
                                acc[i][6] * scale, acc[i][7] * scale);
        *(float4*)&C[(size_t)m * N + bn + tx * 4] = c0;
        *(float4*)&C[(size_t)m * N + bn + 64 + tx * 4] = c1;
    }
}

// Fused: row softmax over logits S + sparse O = P@X.
// One CTA (256 thr) per row. Exploits the near-one-hot softmax: only weights
// > 1e-10 are accumulated (dropped mass <= 8192e-10 ~ 8e-7, invisible at 1e-3).
// Dense fallback if a row has > CAP significant entries (correct for any input).
__global__ __launch_bounds__(256)
void softmax_gather(const float* __restrict__ S, const float* __restrict__ X,
                    float* __restrict__ O)
{
    __shared__ float red[256];
    __shared__ int   s_cnt;
    __shared__ int   s_idx[CAP];
    __shared__ float s_w[CAP];

    const int row = blockIdx.x;
    const int tid = threadIdx.x;
    const float4* p = (const float4*)(S + (size_t)row * NTOK);

    float4 v[8];
    float mx = -3.402823466e+38f;
#pragma unroll
    for (int i = 0; i < 8; i++) {
        v[i] = p[tid + i * 256];
        mx = fmaxf(mx, fmaxf(fmaxf(v[i].x, v[i].y), fmaxf(v[i].z, v[i].w)));
    }
    red[tid] = mx;
    __syncthreads();
    for (int s = 128; s > 0; s >>= 1) {
        if (tid < s) red[tid] = fmaxf(red[tid], red[tid + s]);
        __syncthreads();
    }
    mx = red[0];
    __syncthreads();

    float sum = 0.f;
#pragma unroll
    for (int i = 0; i < 8; i++) {
        v[i].x = expf(v[i].x - mx);
        v[i].y = expf(v[i].y - mx);
        v[i].z = expf(v[i].z - mx);
        v[i].w = expf(v[i].w - mx);
        sum += (v[i].x + v[i].y) + (v[i].z + v[i].w);
    }
    red[tid] = sum;
    if (tid == 0) s_cnt = 0;
    __syncthreads();
    for (int s = 128; s > 0; s >>= 1) {
        if (tid < s) red[tid] += red[tid + s];
        __syncthreads();
    }
    const float inv = 1.f / red[0];

    // Collect significant candidates (w > 1e-10)
#pragma unroll
    for (int i = 0; i < 8; i++) {
        float w4[4] = {v[i].x * inv, v[i].y * inv, v[i].z * inv, v[i].w * inv};
#pragma unroll
        for (int c = 0; c < 4; c++) {
            if (w4[c] > 1e-10f) {
                int k = atomicAdd(&s_cnt, 1);
                if (k < CAP) {
                    s_idx[k] = (tid + i * 256) * 4 + c;
                    s_w[k]   = w4[c];
                }
            }
        }
    }
    __syncthreads();
    const int cnt = s_cnt;

    // Each thread owns 4 output columns
    const int col = tid * 4;
    float a0 = 0.f, a1 = 0.f, a2 = 0.f, a3 = 0.f;
    if (cnt <= CAP) {
        for (int t = 0; t < cnt; t++) {
            const float w = s_w[t];
            const float4 x = *(const float4*)(X + (size_t)s_idx[t] * EMBED + col);
            a0 = fmaf(w, x.x, a0);
            a1 = fmaf(w, x.y, a1);
            a2 = fmaf(w, x.z, a2);
            a3 = fmaf(w, x.w, a3);
        }
    } else {
        // dense fallback: exact for flat rows
        for (int j = 0; j < NTOK; j++) {
            const float w = expf(S[(size_t)row * NTOK + j] - mx) * inv;
            const float4 x = *(const float4*)(X + (size_t)j * EMBED + col);
            a0 = fmaf(w, x.x, a0);
            a1 = fmaf(w, x.y, a1);
            a2 = fmaf(w, x.z, a2);
            a3 = fmaf(w, x.w, a3);
        }
    }
    *(float4*)(O + (size_t)row * EMBED + col) = make_float4(a0, a1, a2, a3);
}

extern "C" void kernel_launch(void* const* d_in, const int* in_sizes, int n_in,
                              void* d_out, int out_size)
{
    const float* Wr = (const float*)d_in[0];   // rotation_params [1024,1024]
    const float* We = (const float*)d_in[1];   // entangle_params [1024,1024]
    const float* X  = (const float*)d_in[2];   // inputs [8192,1024]
    float* out = (float*)d_out;                // [8192,1024] fp32

    float *Qp, *Kp, *Sp;
    cudaGetSymbolAddress((void**)&Qp, g_Q);
    cudaGetSymbolAddress((void**)&Kp, g_K);
    cudaGetSymbolAddress((void**)&Sp, g_S);

    dim3 blk(256);
    // Q = X @ Wr ; K = X @ We
    sgemm128<0><<<dim3(EMBED / 128, NTOK / 128), blk>>>(X, Wr, Qp, NTOK, EMBED, EMBED, 1.0f);
    sgemm128<0><<<dim3(EMBED / 128, NTOK / 128), blk>>>(X, We, Kp, NTOK, EMBED, EMBED, 1.0f);
    // S = (Q @ K^T) / 32  (raw logits)
    sgemm128<1><<<dim3(NTOK / 128, NTOK / 128), blk>>>(Qp, Kp, Sp, NTOK, NTOK, EMBED, 0.03125f);
    // fused softmax + sparse O = P @ X
    softmax_gather<<<NTOK, 256>>>(Sp, X, out);
}

// round 6
// speedup vs baseline: 4.9856x; 2.6809x over previous
#include <cuda_runtime.h>
#include <cuda_bf16.h>
#include <math.h>
#include <stdint.h>

#define EMBED 1024
#define NTOK  8192
#define BK8   8
#define LDSS  132
#define CAP   64      // max finalists per row before exact-dense fallback
#define WINDOW 60.0f

// ---------------- scratch (device globals; no allocation allowed) ----------------
__device__ float          g_Q[(size_t)NTOK * EMBED];
__device__ float          g_K[(size_t)NTOK * EMBED];
__device__ __nv_bfloat16  g_Qb[(size_t)NTOK * EMBED];
__device__ __nv_bfloat16  g_Kb[(size_t)NTOK * EMBED];
__device__ float          g_S[(size_t)NTOK * NTOK];
__device__ unsigned       g_rowmax[NTOK];

// ---------------- helpers ----------------
__device__ __forceinline__ uint32_t smem_u32(const void* p) {
    uint32_t a;
    asm("{ .reg .u64 t; cvta.to.shared.u64 t, %1; cvt.u32.u64 %0, t; }" : "=r"(a) : "l"(p));
    return a;
}
__device__ __forceinline__ void cp_async16(uint32_t s, const void* g) {
    asm volatile("cp.async.cg.shared.global [%0], [%1], 16;" :: "r"(s), "l"(g));
}
__device__ __forceinline__ void cp_commit() { asm volatile("cp.async.commit_group;" ::: "memory"); }
template<int N>
__device__ __forceinline__ void cp_wait() { asm volatile("cp.async.wait_group %0;" :: "n"(N) : "memory"); }

__device__ __forceinline__ void ldsm_x4(uint32_t& r0, uint32_t& r1, uint32_t& r2, uint32_t& r3, uint32_t a) {
    asm volatile("ldmatrix.sync.aligned.m8n8.x4.shared.b16 {%0,%1,%2,%3}, [%4];"
                 : "=r"(r0), "=r"(r1), "=r"(r2), "=r"(r3) : "r"(a));
}
__device__ __forceinline__ void ldsm_x2(uint32_t& r0, uint32_t& r1, uint32_t a) {
    asm volatile("ldmatrix.sync.aligned.m8n8.x2.shared.b16 {%0,%1}, [%2];"
                 : "=r"(r0), "=r"(r1) : "r"(a));
}
__device__ __forceinline__ void mma_bf16(float* d, const uint32_t* a, const uint32_t* b) {
    asm volatile(
        "mma.sync.aligned.m16n8k16.row.col.f32.bf16.bf16.f32 "
        "{%0,%1,%2,%3}, {%4,%5,%6,%7}, {%8,%9}, {%0,%1,%2,%3};"
        : "+f"(d[0]), "+f"(d[1]), "+f"(d[2]), "+f"(d[3])
        : "r"(a[0]), "r"(a[1]), "r"(a[2]), "r"(a[3]), "r"(b[0]), "r"(b[1]));
}

// ordered-int encoding for fp32 atomicMax (0 is below every encoded float)
__device__ __forceinline__ unsigned enc_ord(float f) {
    unsigned u = __float_as_uint(f);
    return (u & 0x80000000u) ? ~u : (u | 0x80000000u);
}
__device__ __forceinline__ float dec_ord(unsigned k) {
    unsigned u = (k & 0x80000000u) ? (k ^ 0x80000000u) : ~k;
    return __uint_as_float(u);
}

// chunk swizzle: rows are 64B (32 bf16); place the 4 16B-chunks so any 8
// consecutive rows at a fixed chunk index hit 8 distinct 16B bank-groups.
#define SWZ(row, kbyte) ((kbyte) ^ ((((row) >> 1) & 3) << 4))

// ---------------- fp32 SIMT GEMM (exact Q, K) ----------------
__global__ __launch_bounds__(256)
void sgemm128(const float* __restrict__ A, const float* __restrict__ B,
              float* __restrict__ C, int M, int N, int Kd)
{
    __shared__ float As[BK8 * LDSS];
    __shared__ float Bs[BK8 * LDSS];

    const int tid = threadIdx.x;
    const int bm = blockIdx.y * 128;
    const int bn = blockIdx.x * 128;
    const int tx = tid & 15;
    const int ty = tid >> 4;

    const int ar = tid >> 1;
    const int ak = (tid & 1) * 4;
    const float* Ap = A + (size_t)(bm + ar) * Kd + ak;

    const int br = tid >> 5;
    const int bk = (tid & 31) * 4;
    const float* Bp = B + (size_t)br * N + (bn + bk);

    float acc[8][8];
#pragma unroll
    for (int i = 0; i < 8; i++)
#pragma unroll
        for (int j = 0; j < 8; j++) acc[i][j] = 0.f;

    float4 areg = *(const float4*)Ap;
    float4 breg = *(const float4*)Bp;

    As[(ak + 0) * LDSS + ar] = areg.x;
    As[(ak + 1) * LDSS + ar] = areg.y;
    As[(ak + 2) * LDSS + ar] = areg.z;
    As[(ak + 3) * LDSS + ar] = areg.w;
    *(float4*)&Bs[br * LDSS + bk] = breg;

    const int ktiles = Kd / BK8;
    for (int kt = 0; kt < ktiles; ++kt) {
        __syncthreads();
        if (kt + 1 < ktiles) {
            Ap += BK8; areg = *(const float4*)Ap;
            Bp += (size_t)BK8 * N; breg = *(const float4*)Bp;
        }
#pragma unroll
        for (int kk = 0; kk < BK8; ++kk) {
            float4 a0 = *(const float4*)&As[kk * LDSS + ty * 4];
            float4 a1 = *(const float4*)&As[kk * LDSS + 64 + ty * 4];
            float4 b0 = *(const float4*)&Bs[kk * LDSS + tx * 4];
            float4 b1 = *(const float4*)&Bs[kk * LDSS + 64 + tx * 4];
            float a[8] = {a0.x, a0.y, a0.z, a0.w, a1.x, a1.y, a1.z, a1.w};
            float b[8] = {b0.x, b0.y, b0.z, b0.w, b1.x, b1.y, b1.z, b1.w};
#pragma unroll
            for (int i = 0; i < 8; i++)
#pragma unroll
                for (int j = 0; j < 8; j++)
                    acc[i][j] = fmaf(a[i], b[j], acc[i][j]);
        }
        __syncthreads();
        if (kt + 1 < ktiles) {
            As[(ak + 0) * LDSS + ar] = areg.x;
            As[(ak + 1) * LDSS + ar] = areg.y;
            As[(ak + 2) * LDSS + ar] = areg.z;
            As[(ak + 3) * LDSS + ar] = areg.w;
            *(float4*)&Bs[br * LDSS + bk] = breg;
        }
    }

#pragma unroll
    for (int i = 0; i < 8; i++) {
        int m = bm + ((i < 4) ? (ty * 4 + i) : (64 + ty * 4 + i - 4));
        *(float4*)&C[(size_t)m * N + bn + tx * 4] =
            make_float4(acc[i][0], acc[i][1], acc[i][2], acc[i][3]);
        *(float4*)&C[(size_t)m * N + bn + 64 + tx * 4] =
            make_float4(acc[i][4], acc[i][5], acc[i][6], acc[i][7]);
    }
}

// ---------------- fp32 -> bf16 convert + rowmax init ----------------
__global__ __launch_bounds__(256)
void conv_bf16(const float* __restrict__ src, __nv_bfloat16* __restrict__ dst)
{
    size_t i = ((size_t)blockIdx.x * blockDim.x + threadIdx.x) * 4;
    float4 v = *(const float4*)(src + i);
    *(__nv_bfloat162*)(dst + i)     = __floats2bfloat162_rn(v.x, v.y);
    *(__nv_bfloat162*)(dst + i + 2) = __floats2bfloat162_rn(v.z, v.w);
}
__global__ void init_rowmax(unsigned* rm) { rm[blockIdx.x * 256 + threadIdx.x] = 0u; }

// ---------------- HMMA bf16: S = (Q K^T)/32, CTA tile 128x128, BK=32 ----------------
// 8 warps as 4(m) x 2(n); warp tile 32x64 = 2x8 m16n8k16 per k16-step.
#define QK_BK 32
#define TILE_B (128 * 64)            // one operand tile: 128 rows x 64B
__global__ __launch_bounds__(256, 2)
void qk_hmma(const __nv_bfloat16* __restrict__ Qb, const __nv_bfloat16* __restrict__ Kb,
             float* __restrict__ S, unsigned* __restrict__ rowmax)
{
    __shared__ __align__(128) char smem[2 * 2 * TILE_B];   // [buf][Q|K]
    const uint32_t sb = smem_u32(smem);

    const int tid  = threadIdx.x;
    const int wid  = tid >> 5;
    const int lane = tid & 31;
    const int wm   = wid >> 1;          // 0..3
    const int wn   = wid & 1;           // 0..1
    const int bm   = blockIdx.y * 128;
    const int bn   = blockIdx.x * 128;

    // gmem->smem chunk mapping (per 128x32bf16 tile: 512 x 16B chunks)
    const int c_row = tid >> 1;                 // two chunks per thread per half
    // ldmatrix lane addressing (offsets within a tile buffer)
    const int a_mrow = (lane & 7) + ((lane >> 3) & 1) * 8; // row within 16-row mma tile
    const int a_kch  = (lane >> 4) & 1;                    // 16B chunk (k0/k8)
    const int b_nrow = lane & 7;
    const int b_kch  = (lane >> 3) & 1;

    float acc[2][8][4];
#pragma unroll
    for (int i = 0; i < 2; i++)
#pragma unroll
        for (int j = 0; j < 8; j++)
#pragma unroll
            for (int c = 0; c < 4; c++) acc[i][j][c] = 0.f;

    // prologue: load chunk 0 into buf 0
    {
        const uint32_t qdst = sb;                 // buf0 Q
        const uint32_t kdst = sb + TILE_B;        // buf0 K
#pragma unroll
        for (int h = 0; h < 2; h++) {
            int cid = tid + h * 256;              // 0..511
            int row = cid >> 2, ck = cid & 3;
            cp_async16(qdst + row * 64 + SWZ(row, ck * 16),
                       Qb + (size_t)(bm + row) * EMBED + ck * 8);
            cp_async16(kdst + row * 64 + SWZ(row, ck * 16),
                       Kb + (size_t)(bn + row) * EMBED + ck * 8);
        }
        cp_commit();
    }

    const int NCH = EMBED / QK_BK;   // 32
    for (int kb = 0; kb < NCH; ++kb) {
        if (kb + 1 < NCH) {
            const int nb = (kb + 1) & 1;
            const uint32_t qdst = sb + nb * 2 * TILE_B;
            const uint32_t kdst = qdst + TILE_B;
            const int koff = (kb + 1) * QK_BK;
#pragma unroll
            for (int h = 0; h < 2; h++) {
                int cid = tid + h * 256;
                int row = cid >> 2, ck = cid & 3;
                cp_async16(qdst + row * 64 + SWZ(row, ck * 16),
                           Qb + (size_t)(bm + row) * EMBED + koff + ck * 8);
                cp_async16(kdst + row * 64 + SWZ(row, ck * 16),
                           Kb + (size_t)(bn + row) * EMBED + koff + ck * 8);
            }
            cp_commit();
            cp_wait<1>();
        } else {
            cp_wait<0>();
        }
        __syncthreads();

        const int buf = kb & 1;
        const uint32_t qbase = sb + buf * 2 * TILE_B;
        const uint32_t kbase = qbase + TILE_B;

#pragma unroll
        for (int ks = 0; ks < 2; ks++) {           // two k16 steps in BK=32
            uint32_t afr[2][4];
#pragma unroll
            for (int mt = 0; mt < 2; mt++) {
                int row = wm * 32 + mt * 16 + a_mrow;
                uint32_t addr = qbase + row * 64 + SWZ(row, ks * 32 + a_kch * 16);
                ldsm_x4(afr[mt][0], afr[mt][1], afr[mt][2], afr[mt][3], addr);
            }
            uint32_t bfr[8][2];
#pragma unroll
            for (int nt = 0; nt < 8; nt++) {
                int row = wn * 64 + nt * 8 + b_nrow;
                uint32_t addr = kbase + row * 64 + SWZ(row, ks * 32 + b_kch * 16);
                ldsm_x2(bfr[nt][0], bfr[nt][1], addr);
            }
#pragma unroll
            for (int mt = 0; mt < 2; mt++)
#pragma unroll
                for (int nt = 0; nt < 8; nt++)
                    mma_bf16(acc[mt][nt], afr[mt], bfr[nt]);
        }
        __syncthreads();
    }

    // epilogue: scale, store, per-row max
    const int g  = lane >> 2;
    const int t4 = lane & 3;
    float rmax[4] = {-3.4e38f, -3.4e38f, -3.4e38f, -3.4e38f};

#pragma unroll
    for (int mt = 0; mt < 2; mt++) {
        const int r0 = bm + wm * 32 + mt * 16 + g;
#pragma unroll
        for (int nt = 0; nt < 8; nt++) {
            const int cc = bn + wn * 64 + nt * 8 + t4 * 2;
            float v0 = acc[mt][nt][0] * 0.03125f;
            float v1 = acc[mt][nt][1] * 0.03125f;
            float v2 = acc[mt][nt][2] * 0.03125f;
            float v3 = acc[mt][nt][3] * 0.03125f;
            *(float2*)(S + (size_t)r0 * NTOK + cc)       = make_float2(v0, v1);
            *(float2*)(S + (size_t)(r0 + 8) * NTOK + cc) = make_float2(v2, v3);
            rmax[mt * 2 + 0] = fmaxf(rmax[mt * 2 + 0], fmaxf(v0, v1));
            rmax[mt * 2 + 1] = fmaxf(rmax[mt * 2 + 1], fmaxf(v2, v3));
        }
    }
#pragma unroll
    for (int s = 0; s < 4; s++) {
        rmax[s] = fmaxf(rmax[s], __shfl_xor_sync(0xffffffff, rmax[s], 1));
        rmax[s] = fmaxf(rmax[s], __shfl_xor_sync(0xffffffff, rmax[s], 2));
    }
    if (t4 == 0) {
#pragma unroll
        for (int mt = 0; mt < 2; mt++) {
            atomicMax(&rowmax[bm + wm * 32 + mt * 16 + g],     enc_ord(rmax[mt * 2 + 0]));
            atomicMax(&rowmax[bm + wm * 32 + mt * 16 + g + 8], enc_ord(rmax[mt * 2 + 1]));
        }
    }
}

// ---------------- select finalists + exact rescore + softmax + gather ----------------
__global__ __launch_bounds__(256)
void select_rescore_gather(const float* __restrict__ S, const unsigned* __restrict__ rowmax,
                           const float* __restrict__ Q, const float* __restrict__ K,
                           const float* __restrict__ X, float* __restrict__ O)
{
    __shared__ float red[256];
    __shared__ int   s_cnt;
    __shared__ int   s_idx[CAP];
    __shared__ float s_lg[CAP];

    const int row = blockIdx.x;
    const int tid = threadIdx.x;
    const float thr = dec_ord(rowmax[row]) - WINDOW;
    const float4* p = (const float4*)(S + (size_t)row * NTOK);

    if (tid == 0) s_cnt = 0;
    __syncthreads();

#pragma unroll
    for (int i = 0; i < 8; i++) {
        float4 v = p[tid + i * 256];
        float vv[4] = {v.x, v.y, v.z, v.w};
#pragma unroll
        for (int c = 0; c < 4; c++) {
            if (vv[c] > thr) {
                int k = atomicAdd(&s_cnt, 1);
                if (k < CAP) s_idx[k] = (tid + i * 256) * 4 + c;
            }
        }
    }
    __syncthreads();
    const int cnt = s_cnt;
    const int col = tid * 4;

    if (cnt <= CAP) {
        const float4 q4 = *(const float4*)(Q + (size_t)row * EMBED + col);
        for (int t = 0; t < cnt; t++) {
            const float4 k4 = *(const float4*)(K + (size_t)s_idx[t] * EMBED + col);
            red[tid] = q4.x * k4.x + q4.y * k4.y + q4.z * k4.z + q4.w * k4.w;
            __syncthreads();
            for (int s = 128; s > 0; s >>= 1) {
                if (tid < s) red[tid] += red[tid + s];
                __syncthreads();
            }
            if (tid == 0) s_lg[t] = red[0] * 0.03125f;
            __syncthreads();
        }
        float mx = -3.402823466e+38f;
        for (int t = 0; t < cnt; t++) mx = fmaxf(mx, s_lg[t]);
        float sum = 0.f;
        for (int t = 0; t < cnt; t++) sum += expf(s_lg[t] - mx);
        const float inv = 1.f / sum;

        float a0 = 0.f, a1 = 0.f, a2 = 0.f, a3 = 0.f;
        for (int t = 0; t < cnt; t++) {
            const float w = expf(s_lg[t] - mx) * inv;
            const float4 x = *(const float4*)(X + (size_t)s_idx[t] * EMBED + col);
            a0 = fmaf(w, x.x, a0); a1 = fmaf(w, x.y, a1);
            a2 = fmaf(w, x.z, a2); a3 = fmaf(w, x.w, a3);
        }
        *(float4*)(O + (size_t)row * EMBED + col) = make_float4(a0, a1, a2, a3);
    } else {
        // pathological fallback: exact dense logits + dense softmax-gather
        float* Srow = (float*)(S + (size_t)row * NTOK);
        const float* qr = Q + (size_t)row * EMBED;
        for (int j = tid; j < NTOK; j += 256) {
            const float* kr = K + (size_t)j * EMBED;
            float d = 0.f;
            for (int e = 0; e < EMBED; e += 4) {
                float4 a = *(const float4*)(qr + e);
                float4 b = *(const float4*)(kr + e);
                d += a.x * b.x + a.y * b.y + a.z * b.z + a.w * b.w;
            }
            Srow[j] = d * 0.03125f;
        }
        __syncthreads();
        float mx = -3.402823466e+38f;
        for (int j = tid; j < NTOK; j += 256) mx = fmaxf(mx, Srow[j]);
        red[tid] = mx; __syncthreads();
        for (int s = 128; s > 0; s >>= 1) {
            if (tid < s) red[tid] = fmaxf(red[tid], red[tid + s]);
            __syncthreads();
        }
        mx = red[0]; __syncthreads();
        float sum = 0.f;
        for (int j = tid; j < NTOK; j += 256) sum += expf(Srow[j] - mx);
        red[tid] = sum; __syncthreads();
        for (int s = 128; s > 0; s >>= 1) {
            if (tid < s) red[tid] += red[tid + s];
            __syncthreads();
        }
        const float inv = 1.f / red[0];
        float a0 = 0.f, a1 = 0.f, a2 = 0.f, a3 = 0.f;
        for (int j = 0; j < NTOK; j++) {
            const float w = expf(Srow[j] - mx) * inv;
            const float4 x = *(const float4*)(X + (size_t)j * EMBED + col);
            a0 = fmaf(w, x.x, a0); a1 = fmaf(w, x.y, a1);
            a2 = fmaf(w, x.z, a2); a3 = fmaf(w, x.w, a3);
        }
        *(float4*)(O + (size_t)row * EMBED + col) = make_float4(a0, a1, a2, a3);
    }
}

// ---------------- launch ----------------
extern "C" void kernel_launch(void* const* d_in, const int* in_sizes, int n_in,
                              void* d_out, int out_size)
{
    const float* Wr = (const float*)d_in[0];
    const float* We = (const float*)d_in[1];
    const float* X  = (const float*)d_in[2];
    float* out = (float*)d_out;

    float *Qp, *Kp, *Sp;
    __nv_bfloat16 *Qbp, *Kbp;
    unsigned* rmx;
    cudaGetSymbolAddress((void**)&Qp,  g_Q);
    cudaGetSymbolAddress((void**)&Kp,  g_K);
    cudaGetSymbolAddress((void**)&Sp,  g_S);
    cudaGetSymbolAddress((void**)&Qbp, g_Qb);
    cudaGetSymbolAddress((void**)&Kbp, g_Kb);
    cudaGetSymbolAddress((void**)&rmx, g_rowmax);

    dim3 blk(256);
    // exact fp32 Q, K
    sgemm128<<<dim3(EMBED / 128, NTOK / 128), blk>>>(X, Wr, Qp, NTOK, EMBED, EMBED);
    sgemm128<<<dim3(EMBED / 128, NTOK / 128), blk>>>(X, We, Kp, NTOK, EMBED, EMBED);
    // bf16 copies + rowmax init
    conv_bf16<<<(NTOK * EMBED) / (256 * 4), blk>>>(Qp, Qbp);
    conv_bf16<<<(NTOK * EMBED) / (256 * 4), blk>>>(Kp, Kbp);
    init_rowmax<<<NTOK / 256, blk>>>(rmx);
    // approx logits via HMMA bf16 + per-row max
    qk_hmma<<<dim3(NTOK / 128, NTOK / 128), blk>>>(Qbp, Kbp, Sp, rmx);
    // finalists: exact rescore + softmax + gather
    select_rescore_gather<<<NTOK, blk>>>(Sp, rmx, Qp, Kp, X, out);
}

// round 8
// speedup vs baseline: 5.8302x; 1.1694x over previous
#include <cuda_runtime.h>
#include <cuda_bf16.h>
#include <math.h>
#include <stdint.h>

#define EMBED 1024
#define NTOK  8192
#define CAP   64
#define WINDOW 100.0f

// ---------------- scratch (device globals; no allocation allowed) ----------------
__device__ float          g_Q[(size_t)NTOK * EMBED];
__device__ float          g_K[(size_t)NTOK * EMBED];
__device__ __nv_bfloat16  g_Qb[(size_t)NTOK * EMBED];
__device__ __nv_bfloat16  g_Kb[(size_t)NTOK * EMBED];
__device__ __nv_bfloat16  g_S[(size_t)NTOK * NTOK];
__device__ unsigned       g_rowmax[NTOK];

// ---------------- helpers ----------------
__device__ __forceinline__ uint32_t smem_u32(const void* p) {
    uint32_t a;
    asm("{ .reg .u64 t; cvta.to.shared.u64 t, %1; cvt.u32.u64 %0, t; }" : "=r"(a) : "l"(p));
    return a;
}
__device__ __forceinline__ void cp_async16(uint32_t s, const void* g) {
    asm volatile("cp.async.cg.shared.global [%0], [%1], 16;" :: "r"(s), "l"(g));
}
__device__ __forceinline__ void cp_commit() { asm volatile("cp.async.commit_group;" ::: "memory"); }
template<int N>
__device__ __forceinline__ void cp_wait() { asm volatile("cp.async.wait_group %0;" :: "n"(N) : "memory"); }

__device__ __forceinline__ void ldsm_x4(uint32_t& r0, uint32_t& r1, uint32_t& r2, uint32_t& r3, uint32_t a) {
    asm volatile("ldmatrix.sync.aligned.m8n8.x4.shared.b16 {%0,%1,%2,%3}, [%4];"
                 : "=r"(r0), "=r"(r1), "=r"(r2), "=r"(r3) : "r"(a));
}
__device__ __forceinline__ void ldsm_x2(uint32_t& r0, uint32_t& r1, uint32_t a) {
    asm volatile("ldmatrix.sync.aligned.m8n8.x2.shared.b16 {%0,%1}, [%2];"
                 : "=r"(r0), "=r"(r1) : "r"(a));
}
__device__ __forceinline__ void mma_bf16(float* d, const uint32_t* a, const uint32_t* b) {
    asm volatile(
        "mma.sync.aligned.m16n8k16.row.col.f32.bf16.bf16.f32 "
        "{%0,%1,%2,%3}, {%4,%5,%6,%7}, {%8,%9}, {%0,%1,%2,%3};"
        : "+f"(d[0]), "+f"(d[1]), "+f"(d[2]), "+f"(d[3])
        : "r"(a[0]), "r"(a[1]), "r"(a[2]), "r"(a[3]), "r"(b[0]), "r"(b[1]));
}
__device__ __forceinline__ void mma_tf32(float* d, const uint32_t* a, const uint32_t* b) {
    asm volatile(
        "mma.sync.aligned.m16n8k8.row.col.f32.tf32.tf32.f32 "
        "{%0,%1,%2,%3}, {%4,%5,%6,%7}, {%8,%9}, {%0,%1,%2,%3};"
        : "+f"(d[0]), "+f"(d[1]), "+f"(d[2]), "+f"(d[3])
        : "r"(a[0]), "r"(a[1]), "r"(a[2]), "r"(a[3]), "r"(b[0]), "r"(b[1]));
}
__device__ __forceinline__ void split_tf32(float x, uint32_t& hi, uint32_t& lo) {
    asm("cvt.rna.tf32.f32 %0, %1;" : "=r"(hi) : "f"(x));
    float r = x - __uint_as_float(hi);
    asm("cvt.rna.tf32.f32 %0, %1;" : "=r"(lo) : "f"(r));
}

// ordered-int encoding for fp32 atomicMax (0 below every encoded value)
__device__ __forceinline__ unsigned enc_ord(float f) {
    unsigned u = __float_as_uint(f);
    return (u & 0x80000000u) ? ~u : (u | 0x80000000u);
}
__device__ __forceinline__ float dec_ord(unsigned k) {
    unsigned u = (k & 0x80000000u) ? (k ^ 0x80000000u) : ~k;
    return __uint_as_float(u);
}

#define SWZ(row, kbyte) ((kbyte) ^ ((((row) >> 1) & 3) << 4))

// ---------------- 3xTF32 GEMM: C = A[M,K] @ B[K,N], fp32-accurate, + bf16 copy ----------------
// CTA 128x128, BK=16, 8 warps (4m x 2n), warp tile 32x64.
#define GLDA 20
#define GLDB 136
__global__ __launch_bounds__(256, 1)
void xw_tf32(const float* __restrict__ A, const float* __restrict__ B,
             float* __restrict__ C, __nv_bfloat16* __restrict__ Cb)
{
    __shared__ __align__(16) float As[2][128 * GLDA];
    __shared__ __align__(16) float Bs[2][16 * GLDB];
    const uint32_t sa = smem_u32(As);
    const uint32_t sbm = smem_u32(Bs);

    const int tid  = threadIdx.x;
    const int wid  = tid >> 5;
    const int lane = tid & 31;
    const int wm   = wid >> 1;
    const int wn   = wid & 1;
    const int bm   = blockIdx.y * 128;
    const int bn   = blockIdx.x * 128;
    const int fr   = lane >> 2;
    const int fk   = lane & 3;

    const int N = EMBED, Kd = EMBED;

    float acc[2][8][4];
#pragma unroll
    for (int i = 0; i < 2; i++)
#pragma unroll
        for (int j = 0; j < 8; j++)
#pragma unroll
            for (int c = 0; c < 4; c++) acc[i][j][c] = 0.f;

    // prologue loads (buf 0): A 512 chunks, B 512 chunks
#pragma unroll
    for (int h = 0; h < 2; h++) {
        int cid = tid + h * 256;
        int r = cid >> 2, kc = cid & 3;
        cp_async16(sa + r * (GLDA * 4) + kc * 16, A + (size_t)(bm + r) * Kd + kc * 4);
        int r2 = cid >> 5, nc = cid & 31;
        cp_async16(sbm + r2 * (GLDB * 4) + nc * 16, B + (size_t)r2 * N + bn + nc * 4);
    }
    cp_commit();

    const int NKB = Kd / 16;
    for (int kb = 0; kb < NKB; ++kb) {
        if (kb + 1 < NKB) {
            const int nb = (kb + 1) & 1;
            const int ko = (kb + 1) * 16;
#pragma unroll
            for (int h = 0; h < 2; h++) {
                int cid = tid + h * 256;
                int r = cid >> 2, kc = cid & 3;
                cp_async16(sa + nb * (128 * GLDA * 4) + r * (GLDA * 4) + kc * 16,
                           A + (size_t)(bm + r) * Kd + ko + kc * 4);
                int r2 = cid >> 5, nc = cid & 31;
                cp_async16(sbm + nb * (16 * GLDB * 4) + r2 * (GLDB * 4) + nc * 16,
                           B + (size_t)(ko + r2) * N + bn + nc * 4);
            }
            cp_commit();
            cp_wait<1>();
        } else {
            cp_wait<0>();
        }
        __syncthreads();

        const int buf = kb & 1;
#pragma unroll
        for (int ks = 0; ks < 2; ks++) {
            uint32_t ahi[2][4], alo[2][4];
#pragma unroll
            for (int mt = 0; mt < 2; mt++) {
                const int r0 = wm * 32 + mt * 16 + fr;
                float a0 = As[buf][r0 * GLDA + ks * 8 + fk];
                float a1 = As[buf][(r0 + 8) * GLDA + ks * 8 + fk];
                float a2 = As[buf][r0 * GLDA + ks * 8 + 4 + fk];
                float a3 = As[buf][(r0 + 8) * GLDA + ks * 8 + 4 + fk];
                split_tf32(a0, ahi[mt][0], alo[mt][0]);
                split_tf32(a1, ahi[mt][1], alo[mt][1]);
                split_tf32(a2, ahi[mt][2], alo[mt][2]);
                split_tf32(a3, ahi[mt][3], alo[mt][3]);
            }
            uint32_t bhi[8][2], blo[8][2];
#pragma unroll
            for (int nt = 0; nt < 8; nt++) {
                const int c0 = wn * 64 + nt * 8 + fr;
                float b0 = Bs[buf][(ks * 8 + fk) * GLDB + c0];
                float b1 = Bs[buf][(ks * 8 + 4 + fk) * GLDB + c0];
                split_tf32(b0, bhi[nt][0], blo[nt][0]);
                split_tf32(b1, bhi[nt][1], blo[nt][1]);
            }
#pragma unroll
            for (int mt = 0; mt < 2; mt++)
#pragma unroll
                for (int nt = 0; nt < 8; nt++) {
                    mma_tf32(acc[mt][nt], ahi[mt], blo[nt]);
                    mma_tf32(acc[mt][nt], alo[mt], bhi[nt]);
                    mma_tf32(acc[mt][nt], ahi[mt], bhi[nt]);
                }
        }
        __syncthreads();
    }

    // epilogue: fp32 + bf16 copies
    const int fc = (lane & 3) * 2;
#pragma unroll
    for (int mt = 0; mt < 2; mt++) {
        const int r0 = bm + wm * 32 + mt * 16 + fr;
#pragma unroll
        for (int nt = 0; nt < 8; nt++) {
            const int cc = bn + wn * 64 + nt * 8 + fc;
            *(float2*)(C + (size_t)r0 * N + cc)       = make_float2(acc[mt][nt][0], acc[mt][nt][1]);
            *(float2*)(C + (size_t)(r0 + 8) * N + cc) = make_float2(acc[mt][nt][2], acc[mt][nt][3]);
            *(__nv_bfloat162*)(Cb + (size_t)r0 * N + cc) =
                __floats2bfloat162_rn(acc[mt][nt][0], acc[mt][nt][1]);
            *(__nv_bfloat162*)(Cb + (size_t)(r0 + 8) * N + cc) =
                __floats2bfloat162_rn(acc[mt][nt][2], acc[mt][nt][3]);
        }
    }
}

__global__ void init_rowmax(unsigned* rm) { rm[blockIdx.x * 256 + threadIdx.x] = 0u; }

// ---------------- HMMA bf16: S = (Q K^T)/32 (bf16 store), tile 128x128, BK=32 ----------------
#define QK_BK 32
#define TILE_B (128 * 64)
__global__ __launch_bounds__(256, 2)
void qk_hmma(const __nv_bfloat16* __restrict__ Qb, const __nv_bfloat16* __restrict__ Kb,
             __nv_bfloat16* __restrict__ S, unsigned* __restrict__ rowmax)
{
    __shared__ __align__(128) char smem[2 * 2 * TILE_B];
    const uint32_t sb = smem_u32(smem);

    const int tid  = threadIdx.x;
    const int wid  = tid >> 5;
    const int lane = tid & 31;
    const int wm   = wid >> 1;
    const int wn   = wid & 1;
    const int bm   = blockIdx.y * 128;
    const int bn   = blockIdx.x * 128;

    const int a_mrow = (lane & 7) + ((lane >> 3) & 1) * 8;
    const int a_kch  = (lane >> 4) & 1;
    const int b_nrow = lane & 7;
    const int b_kch  = (lane >> 3) & 1;

    float acc[2][8][4];
#pragma unroll
    for (int i = 0; i < 2; i++)
#pragma unroll
        for (int j = 0; j < 8; j++)
#pragma unroll
            for (int c = 0; c < 4; c++) acc[i][j][c] = 0.f;

    {
        const uint32_t qdst = sb, kdst = sb + TILE_B;
#pragma unroll
        for (int h = 0; h < 2; h++) {
            int cid = tid + h * 256;
            int row = cid >> 2, ck = cid & 3;
            cp_async16(qdst + row * 64 + SWZ(row, ck * 16), Qb + (size_t)(bm + row) * EMBED + ck * 8);
            cp_async16(kdst + row * 64 + SWZ(row, ck * 16), Kb + (size_t)(bn + row) * EMBED + ck * 8);
        }
        cp_commit();
    }

    const int NCH = EMBED / QK_BK;
    for (int kb = 0; kb < NCH; ++kb) {
        if (kb + 1 < NCH) {
            const int nb = (kb + 1) & 1;
            const uint32_t qdst = sb + nb * 2 * TILE_B;
            const uint32_t kdst = qdst + TILE_B;
            const int koff = (kb + 1) * QK_BK;
#pragma unroll
            for (int h = 0; h < 2; h++) {
                int cid = tid + h * 256;
                int row = cid >> 2, ck = cid & 3;
                cp_async16(qdst + row * 64 + SWZ(row, ck * 16),
                           Qb + (size_t)(bm + row) * EMBED + koff + ck * 8);
                cp_async16(kdst + row * 64 + SWZ(row, ck * 16),
                           Kb + (size_t)(bn + row) * EMBED + koff + ck * 8);
            }
            cp_commit();
            cp_wait<1>();
        } else {
            cp_wait<0>();
        }
        __syncthreads();

        const int buf = kb & 1;
        const uint32_t qbase = sb + buf * 2 * TILE_B;
        const uint32_t kbase = qbase + TILE_B;

#pragma unroll
        for (int ks = 0; ks < 2; ks++) {
            uint32_t afr[2][4];
#pragma unroll
            for (int mt = 0; mt < 2; mt++) {
                int row = wm * 32 + mt * 16 + a_mrow;
                ldsm_x4(afr[mt][0], afr[mt][1], afr[mt][2], afr[mt][3],
                        qbase + row * 64 + SWZ(row, ks * 32 + a_kch * 16));
            }
            uint32_t bfr[8][2];
#pragma unroll
            for (int nt = 0; nt < 8; nt++) {
                int row = wn * 64 + nt * 8 + b_nrow;
                ldsm_x2(bfr[nt][0], bfr[nt][1],
                        kbase + row * 64 + SWZ(row, ks * 32 + b_kch * 16));
            }
#pragma unroll
            for (int mt = 0; mt < 2; mt++)
#pragma unroll
                for (int nt = 0; nt < 8; nt++)
                    mma_bf16(acc[mt][nt], afr[mt], bfr[nt]);
        }
        __syncthreads();
    }

    const int g  = lane >> 2;
    const int t4 = lane & 3;
    float rmax[4] = {-3.4e38f, -3.4e38f, -3.4e38f, -3.4e38f};

#pragma unroll
    for (int mt = 0; mt < 2; mt++) {
        const int r0 = bm + wm * 32 + mt * 16 + g;
#pragma unroll
        for (int nt = 0; nt < 8; nt++) {
            const int cc = bn + wn * 64 + nt * 8 + t4 * 2;
            float v0 = acc[mt][nt][0] * 0.03125f;
            float v1 = acc[mt][nt][1] * 0.03125f;
            float v2 = acc[mt][nt][2] * 0.03125f;
            float v3 = acc[mt][nt][3] * 0.03125f;
            *(__nv_bfloat162*)(S + (size_t)r0 * NTOK + cc)       = __floats2bfloat162_rn(v0, v1);
            *(__nv_bfloat162*)(S + (size_t)(r0 + 8) * NTOK + cc) = __floats2bfloat162_rn(v2, v3);
            rmax[mt * 2 + 0] = fmaxf(rmax[mt * 2 + 0], fmaxf(v0, v1));
            rmax[mt * 2 + 1] = fmaxf(rmax[mt * 2 + 1], fmaxf(v2, v3));
        }
    }
#pragma unroll
    for (int s = 0; s < 4; s++) {
        rmax[s] = fmaxf(rmax[s], __shfl_xor_sync(0xffffffff, rmax[s], 1));
        rmax[s] = fmaxf(rmax[s], __shfl_xor_sync(0xffffffff, rmax[s], 2));
    }
    if (t4 == 0) {
#pragma unroll
        for (int mt = 0; mt < 2; mt++) {
            atomicMax(&rowmax[bm + wm * 32 + mt * 16 + g],     enc_ord(rmax[mt * 2 + 0]));
            atomicMax(&rowmax[bm + wm * 32 + mt * 16 + g + 8], enc_ord(rmax[mt * 2 + 1]));
        }
    }
}

// ---------------- select finalists + exact rescore + softmax + gather ----------------
__global__ __launch_bounds__(256)
void select_rescore_gather(const __nv_bfloat16* __restrict__ S, const unsigned* __restrict__ rowmax,
                           const float* __restrict__ Q, const float* __restrict__ K,
                           const float* __restrict__ X, float* __restrict__ O)
{
    __shared__ float red[256];
    __shared__ int   s_cnt;
    __shared__ int   s_idx[CAP];
    __shared__ float s_lg[CAP];
    __shared__ float ws[NTOK];   // fallback-only scratch

    const int row = blockIdx.x;
    const int tid = threadIdx.x;
    const float thr = dec_ord(rowmax[row]) - WINDOW;
    const uint4* p = (const uint4*)(S + (size_t)row * NTOK);   // 8 bf16 per uint4

    if (tid == 0) s_cnt = 0;
    __syncthreads();

#pragma unroll
    for (int i = 0; i < 4; i++) {
        uint4 u = p[tid + i * 256];
        float f[8];
        __nv_bfloat162 h;
        h = *(__nv_bfloat162*)&u.x; f[0] = __low2float(h); f[1] = __high2float(h);
        h = *(__nv_bfloat162*)&u.y; f[2] = __low2float(h); f[3] = __high2float(h);
        h = *(__nv_bfloat162*)&u.z; f[4] = __low2float(h); f[5] = __high2float(h);
        h = *(__nv_bfloat162*)&u.w; f[6] = __low2float(h); f[7] = __high2float(h);
#pragma unroll
        for (int c = 0; c < 8; c++) {
            if (f[c] > thr) {
                int k = atomicAdd(&s_cnt, 1);
                if (k < CAP) s_idx[k] = (tid + i * 256) * 8 + c;
            }
        }
    }
    __syncthreads();
    const int cnt = s_cnt;
    const int col = tid * 4;

    if (cnt <= CAP) {
        const float4 q4 = *(const float4*)(Q + (size_t)row * EMBED + col);
        for (int t = 0; t < cnt; t++) {
            const float4 k4 = *(const float4*)(K + (size_t)s_idx[t] * EMBED + col);
            red[tid] = q4.x * k4.x + q4.y * k4.y + q4.z * k4.z + q4.w * k4.w;
            __syncthreads();
            for (int s = 128; s > 0; s >>= 1) {
                if (tid < s) red[tid] += red[tid + s];
                __syncthreads();
            }
            if (tid == 0) s_lg[t] = red[0] * 0.03125f;
            __syncthreads();
        }
        float mx = -3.402823466e+38f;
        for (int t = 0; t < cnt; t++) mx = fmaxf(mx, s_lg[t]);
        float sum = 0.f;
        for (int t = 0; t < cnt; t++) sum += expf(s_lg[t] - mx);
        const float inv = 1.f / sum;

        float a0 = 0.f, a1 = 0.f, a2 = 0.f, a3 = 0.f;
        for (int t = 0; t < cnt; t++) {
            const float w = expf(s_lg[t] - mx) * inv;
            const float4 x = *(const float4*)(X + (size_t)s_idx[t] * EMBED + col);
            a0 = fmaf(w, x.x, a0); a1 = fmaf(w, x.y, a1);
            a2 = fmaf(w, x.z, a2); a3 = fmaf(w, x.w, a3);
        }
        *(float4*)(O + (size_t)row * EMBED + col) = make_float4(a0, a1, a2, a3);
    } else {
        // pathological fallback: exact dense logits into smem + dense softmax-gather
        const float* qr = Q + (size_t)row * EMBED;
        for (int j = tid; j < NTOK; j += 256) {
            const float* kr = K + (size_t)j * EMBED;
            float d = 0.f;
            for (int e = 0; e < EMBED; e += 4) {
                float4 a = *(const float4*)(qr + e);
                float4 b = *(const float4*)(kr + e);
                d += a.x * b.x + a.y * b.y + a.z * b.z + a.w * b.w;
            }
            ws[j] = d * 0.03125f;
        }
        __syncthreads();
        float mx = -3.402823466e+38f;
        for (int j = tid; j < NTOK; j += 256) mx = fmaxf(mx, ws[j]);
        red[tid] = mx; __syncthreads();
        for (int s = 128; s > 0; s >>= 1) {
            if (tid < s) red[tid] = fmaxf(red[tid], red[tid + s]);
            __syncthreads();
        }
        mx = red[0]; __syncthreads();
        float sum = 0.f;
        for (int j = tid; j < NTOK; j += 256) sum += expf(ws[j] - mx);
        red[tid] = sum; __syncthreads();
        for (int s = 128; s > 0; s >>= 1) {
            if (tid < s) red[tid] += red[tid + s];
            __syncthreads();
        }
        const float inv = 1.f / red[0];
        float a0 = 0.f, a1 = 0.f, a2 = 0.f, a3 = 0.f;
        for (int j = 0; j < NTOK; j++) {
            const float w = expf(ws[j] - mx) * inv;
            const float4 x = *(const float4*)(X + (size_t)j * EMBED + col);
            a0 = fmaf(w, x.x, a0); a1 = fmaf(w, x.y, a1);
            a2 = fmaf(w, x.z, a2); a3 = fmaf(w, x.w, a3);
        }
        *(float4*)(O + (size_t)row * EMBED + col) = make_float4(a0, a1, a2, a3);
    }
}

// ---------------- launch ----------------
extern "C" void kernel_launch(void* const* d_in, const int* in_sizes, int n_in,
                              void* d_out, int out_size)
{
    const float* Wr = (const float*)d_in[0];
    const float* We = (const float*)d_in[1];
    const float* X  = (const float*)d_in[2];
    float* out = (float*)d_out;

    float *Qp, *Kp;
    __nv_bfloat16 *Qbp, *Kbp, *Sp;
    unsigned* rmx;
    cudaGetSymbolAddress((void**)&Qp,  g_Q);
    cudaGetSymbolAddress((void**)&Kp,  g_K);
    cudaGetSymbolAddress((void**)&Sp,  g_S);
    cudaGetSymbolAddress((void**)&Qbp, g_Qb);
    cudaGetSymbolAddress((void**)&Kbp, g_Kb);
    cudaGetSymbolAddress((void**)&rmx, g_rowmax);

    dim3 blk(256);
    // exact-fp32-quality Q, K via 3xTF32 tensor GEMM (+ fused bf16 copies)
    xw_tf32<<<dim3(EMBED / 128, NTOK / 128), blk>>>(X, Wr, Qp, Qbp);
    xw_tf32<<<dim3(EMBED / 128, NTOK / 128), blk>>>(X, We, Kp, Kbp);
    init_rowmax<<<NTOK / 256, blk>>>(rmx);
    // approx logits via HMMA bf16, stored bf16, + per-row max
    qk_hmma<<<dim3(NTOK / 128, NTOK / 128), blk>>>(Qbp, Kbp, Sp, rmx);
    // finalists: exact rescore + softmax + gather
    select_rescore_gather<<<NTOK, blk>>>(Sp, rmx, Qp, Kp, X, out);
}

// round 12
// speedup vs baseline: 8.4436x; 1.4483x over previous
#include <cuda_runtime.h>
#include <cuda_bf16.h>
#include <math.h>
#include <stdint.h>

#define EMBED 1024
#define NTOK  8192
#define CAP   64
#define WINDOW 100.0f

// ---------------- scratch (device globals) ----------------
__device__ float          g_Q[(size_t)NTOK * EMBED];
__device__ float          g_K[(size_t)NTOK * EMBED];
__device__ __nv_bfloat16  g_Xhi[(size_t)NTOK * EMBED];
__device__ __nv_bfloat16  g_Xlo[(size_t)NTOK * EMBED];
__device__ __nv_bfloat16  g_Wrhi[(size_t)EMBED * EMBED];
__device__ __nv_bfloat16  g_Wrlo[(size_t)EMBED * EMBED];
__device__ __nv_bfloat16  g_Wehi[(size_t)EMBED * EMBED];
__device__ __nv_bfloat16  g_Welo[(size_t)EMBED * EMBED];
__device__ __nv_bfloat16  g_Qb[(size_t)NTOK * EMBED];
__device__ __nv_bfloat16  g_Kb[(size_t)NTOK * EMBED];
__device__ __nv_bfloat16  g_S[(size_t)NTOK * NTOK];
__device__ unsigned       g_rowmax[NTOK];

// ---------------- helpers ----------------
__device__ __forceinline__ uint32_t smem_u32(const void* p) {
    uint32_t a;
    asm("{ .reg .u64 t; cvta.to.shared.u64 t, %1; cvt.u32.u64 %0, t; }" : "=r"(a) : "l"(p));
    return a;
}
__device__ __forceinline__ void cp_async16(uint32_t s, const void* g) {
    asm volatile("cp.async.cg.shared.global [%0], [%1], 16;" :: "r"(s), "l"(g));
}
__device__ __forceinline__ void cp_commit() { asm volatile("cp.async.commit_group;" ::: "memory"); }
template<int N>
__device__ __forceinline__ void cp_wait() { asm volatile("cp.async.wait_group %0;" :: "n"(N) : "memory"); }

__device__ __forceinline__ void ldsm_x4(uint32_t& r0, uint32_t& r1, uint32_t& r2, uint32_t& r3, uint32_t a) {
    asm volatile("ldmatrix.sync.aligned.m8n8.x4.shared.b16 {%0,%1,%2,%3}, [%4];"
                 : "=r"(r0), "=r"(r1), "=r"(r2), "=r"(r3) : "r"(a));
}
__device__ __forceinline__ void mma_bf16(float* d, const uint32_t* a, uint32_t b0, uint32_t b1) {
    asm volatile(
        "mma.sync.aligned.m16n8k16.row.col.f32.bf16.bf16.f32 "
        "{%0,%1,%2,%3}, {%4,%5,%6,%7}, {%8,%9}, {%0,%1,%2,%3};"
        : "+f"(d[0]), "+f"(d[1]), "+f"(d[2]), "+f"(d[3])
        : "r"(a[0]), "r"(a[1]), "r"(a[2]), "r"(a[3]), "r"(b0), "r"(b1));
}

__device__ __forceinline__ unsigned enc_ord(float f) {
    unsigned u = __float_as_uint(f);
    return (u & 0x80000000u) ? ~u : (u | 0x80000000u);
}
__device__ __forceinline__ float dec_ord(unsigned k) {
    unsigned u = (k & 0x80000000u) ? (k ^ 0x80000000u) : ~k;
    return __uint_as_float(u);
}

#define SWZ(row, kbyte) ((kbyte) ^ ((((row) >> 1) & 3) << 4))
#define TILE_B (128 * 64)       // one 128-row x 32-bf16 tile = 8KB

// ---------------- split converts ----------------
__global__ __launch_bounds__(256)
void conv_split_x(const float* __restrict__ src,
                  __nv_bfloat16* __restrict__ hi, __nv_bfloat16* __restrict__ lo)
{
    size_t i = ((size_t)blockIdx.x * 256 + threadIdx.x) * 4;
    float4 v = *(const float4*)(src + i);
    float f[4] = {v.x, v.y, v.z, v.w};
    __nv_bfloat16 h[4], l[4];
#pragma unroll
    for (int c = 0; c < 4; c++) {
        h[c] = __float2bfloat16(f[c]);
        l[c] = __float2bfloat16(f[c] - __bfloat162float(h[c]));
    }
    *(__nv_bfloat162*)(hi + i)     = *(__nv_bfloat162*)&h[0];
    *(__nv_bfloat162*)(hi + i + 2) = *(__nv_bfloat162*)&h[2];
    *(__nv_bfloat162*)(lo + i)     = *(__nv_bfloat162*)&l[0];
    *(__nv_bfloat162*)(lo + i + 2) = *(__nv_bfloat162*)&l[2];
}

// W[k][n] -> transposed split Whi/Wlo[n][k]
__global__ __launch_bounds__(256)
void conv_split_wT(const float* __restrict__ W,
                   __nv_bfloat16* __restrict__ hi, __nv_bfloat16* __restrict__ lo)
{
    __shared__ float t[32][33];
    const int tx = threadIdx.x & 31, ty = threadIdx.x >> 5;
    const int bk = blockIdx.y * 32, bn = blockIdx.x * 32;
#pragma unroll
    for (int i = 0; i < 4; i++)
        t[ty + 8 * i][tx] = W[(size_t)(bk + ty + 8 * i) * EMBED + bn + tx];
    __syncthreads();
#pragma unroll
    for (int i = 0; i < 4; i++) {
        const int n = bn + ty + 8 * i, k = bk + tx;
        float v = t[tx][ty + 8 * i];
        __nv_bfloat16 h = __float2bfloat16(v);
        __nv_bfloat16 l = __float2bfloat16(v - __bfloat162float(h));
        hi[(size_t)n * EMBED + k] = h;
        lo[(size_t)n * EMBED + k] = l;
    }
}

__global__ void init_rowmax(unsigned* rm) { rm[blockIdx.x * 256 + threadIdx.x] = 0u; }

// ---------------- bf16x3 GEMM: C = X @ W (fp32-quality), + bf16 copy ----------------
// A=Xhi/Xlo [m][k], B=Whi/Wlo [n][k] (pre-transposed). CTA 128x128, BK=32, 3 stages.
#define XW_STAGE (4 * TILE_B)    // Ahi|Alo|Bhi|Blo = 32KB
__global__ __launch_bounds__(256, 2)
void xw_bf16x3(const __nv_bfloat16* __restrict__ Ahi, const __nv_bfloat16* __restrict__ Alo,
               const __nv_bfloat16* __restrict__ Bhi, const __nv_bfloat16* __restrict__ Blo,
               float* __restrict__ C, __nv_bfloat16* __restrict__ Cb)
{
    extern __shared__ __align__(128) char smem[];
    const uint32_t sb = smem_u32(smem);

    const int tid  = threadIdx.x;
    const int lane = tid & 31;
    const int wid  = tid >> 5;
    const int wm   = wid >> 1;
    const int wn   = wid & 1;
    const int bm   = blockIdx.y * 128;
    const int bn   = blockIdx.x * 128;

    const int a_mrow = (lane & 7) + ((lane >> 3) & 1) * 8;
    const int a_kch  = (lane >> 4) & 1;
    const int b_row8 = ((lane >> 4) & 1) * 8 + (lane & 7);
    const int b_kch  = (lane >> 3) & 1;

    const int ld_row = tid >> 2, ld_ck = tid & 3;
    const uint32_t ld_off = ld_row * 64 + SWZ(ld_row, ld_ck * 16);
    const int ld_row2 = (tid + 256) >> 2, ld_ck2 = (tid + 256) & 3;
    const uint32_t ld_off2 = ld_row2 * 64 + SWZ(ld_row2, ld_ck2 * 16);

    float acc[2][8][4];
#pragma unroll
    for (int i = 0; i < 2; i++)
#pragma unroll
        for (int j = 0; j < 8; j++)
#pragma unroll
            for (int c = 0; c < 4; c++) acc[i][j][c] = 0.f;

    const int NCH = EMBED / 32;

#define XW_LOAD(st, kb_)                                                                  \
    do {                                                                                  \
        const uint32_t base = sb + (st) * XW_STAGE;                                       \
        const int ko = (kb_) * 32;                                                        \
        cp_async16(base + ld_off,              Ahi + (size_t)(bm + ld_row)  * EMBED + ko + ld_ck  * 8); \
        cp_async16(base + 8192  + ld_off,      Alo + (size_t)(bm + ld_row)  * EMBED + ko + ld_ck  * 8); \
        cp_async16(base + 16384 + ld_off,      Bhi + (size_t)(bn + ld_row)  * EMBED + ko + ld_ck  * 8); \
        cp_async16(base + 24576 + ld_off,      Blo + (size_t)(bn + ld_row)  * EMBED + ko + ld_ck  * 8); \
        cp_async16(base + ld_off2,             Ahi + (size_t)(bm + ld_row2) * EMBED + ko + ld_ck2 * 8); \
        cp_async16(base + 8192  + ld_off2,     Alo + (size_t)(bm + ld_row2) * EMBED + ko + ld_ck2 * 8); \
        cp_async16(base + 16384 + ld_off2,     Bhi + (size_t)(bn + ld_row2) * EMBED + ko + ld_ck2 * 8); \
        cp_async16(base + 24576 + ld_off2,     Blo + (size_t)(bn + ld_row2) * EMBED + ko + ld_ck2 * 8); \
    } while (0)

    XW_LOAD(0, 0); cp_commit();
    XW_LOAD(1, 1); cp_commit();

    for (int kb = 0; kb < NCH; ++kb) {
        if (kb < NCH - 2) cp_wait<1>(); else cp_wait<0>();
        __syncthreads();
        if (kb + 2 < NCH) { XW_LOAD((kb + 2) % 3, kb + 2); cp_commit(); }

        const uint32_t base = sb + (kb % 3) * XW_STAGE;
#pragma unroll
        for (int ks = 0; ks < 2; ks++) {
            uint32_t ahi[2][4], alo[2][4];
#pragma unroll
            for (int mt = 0; mt < 2; mt++) {
                int row = wm * 32 + mt * 16 + a_mrow;
                uint32_t o = row * 64 + SWZ(row, ks * 32 + a_kch * 16);
                ldsm_x4(ahi[mt][0], ahi[mt][1], ahi[mt][2], ahi[mt][3], base + o);
                ldsm_x4(alo[mt][0], alo[mt][1], alo[mt][2], alo[mt][3], base + 8192 + o);
            }
#pragma unroll
            for (int p = 0; p < 4; p++) {
                int row = wn * 64 + p * 16 + b_row8;
                uint32_t o = row * 64 + SWZ(row, ks * 32 + b_kch * 16);
                uint32_t h0, h1, h2, h3, l0, l1, l2, l3;
                ldsm_x4(h0, h1, h2, h3, base + 16384 + o);
                ldsm_x4(l0, l1, l2, l3, base + 24576 + o);
#pragma unroll
                for (int mt = 0; mt < 2; mt++) {
                    mma_bf16(acc[mt][2 * p],     ahi[mt], h0, h1);
                    mma_bf16(acc[mt][2 * p],     ahi[mt], l0, l1);
                    mma_bf16(acc[mt][2 * p],     alo[mt], h0, h1);
                    mma_bf16(acc[mt][2 * p + 1], ahi[mt], h2, h3);
                    mma_bf16(acc[mt][2 * p + 1], ahi[mt], l2, l3);
                    mma_bf16(acc[mt][2 * p + 1], alo[mt], h2, h3);
                }
            }
        }
        __syncthreads();
    }

    const int fr = lane >> 2, fc = (lane & 3) * 2;
#pragma unroll
    for (int mt = 0; mt < 2; mt++) {
        const int r0 = bm + wm * 32 + mt * 16 + fr;
#pragma unroll
        for (int nt = 0; nt < 8; nt++) {
            const int cc = bn + wn * 64 + nt * 8 + fc;
            *(float2*)(C + (size_t)r0 * EMBED + cc)       = make_float2(acc[mt][nt][0], acc[mt][nt][1]);
            *(float2*)(C + (size_t)(r0 + 8) * EMBED + cc) = make_float2(acc[mt][nt][2], acc[mt][nt][3]);
            *(__nv_bfloat162*)(Cb + (size_t)r0 * EMBED + cc) =
                __floats2bfloat162_rn(acc[mt][nt][0], acc[mt][nt][1]);
            *(__nv_bfloat162*)(Cb + (size_t)(r0 + 8) * EMBED + cc) =
                __floats2bfloat162_rn(acc[mt][nt][2], acc[mt][nt][3]);
        }
    }
}

// ---------------- HMMA bf16: S = (Q K^T)/32 (bf16 store), 128x128, BK=32, 3 stages ----------------
#define QK_STAGE (2 * TILE_B)    // Q|K = 16KB
__global__ __launch_bounds__(256, 2)
void qk_hmma(const __nv_bfloat16* __restrict__ Qb, const __nv_bfloat16* __restrict__ Kb,
             __nv_bfloat16* __restrict__ S, unsigned* __restrict__ rowmax)
{
    __shared__ __align__(128) char smem[3 * QK_STAGE];
    const uint32_t sb = smem_u32(smem);

    const int tid  = threadIdx.x;
    const int lane = tid & 31;
    const int wid  = tid >> 5;
    const int wm   = wid >> 1;
    const int wn   = wid & 1;
    const int bm   = blockIdx.y * 128;
    const int bn   = blockIdx.x * 128;

    const int a_mrow = (lane & 7) + ((lane >> 3) & 1) * 8;
    const int a_kch  = (lane >> 4) & 1;
    const int b_row8 = ((lane >> 4) & 1) * 8 + (lane & 7);
    const int b_kch  = (lane >> 3) & 1;

    const int ld_row = tid >> 2, ld_ck = tid & 3;
    const uint32_t ld_off = ld_row * 64 + SWZ(ld_row, ld_ck * 16);
    const int ld_row2 = (tid + 256) >> 2, ld_ck2 = (tid + 256) & 3;
    const uint32_t ld_off2 = ld_row2 * 64 + SWZ(ld_row2, ld_ck2 * 16);

    float acc[2][8][4];
#pragma unroll
    for (int i = 0; i < 2; i++)
#pragma unroll
        for (int j = 0; j < 8; j++)
#pragma unroll
            for (int c = 0; c < 4; c++) acc[i][j][c] = 0.f;

    const int NCH = EMBED / 32;

#define QK_LOAD(st, kb_)                                                                   \
    do {                                                                                   \
        const uint32_t base = sb + (st) * QK_STAGE;                                        \
        const int ko = (kb_) * 32;                                                         \
        cp_async16(base + ld_off,          Qb + (size_t)(bm + ld_row)  * EMBED + ko + ld_ck  * 8); \
        cp_async16(base + 8192 + ld_off,   Kb + (size_t)(bn + ld_row)  * EMBED + ko + ld_ck  * 8); \
        cp_async16(base + ld_off2,         Qb + (size_t)(bm + ld_row2) * EMBED + ko + ld_ck2 * 8); \
        cp_async16(base + 8192 + ld_off2,  Kb + (size_t)(bn + ld_row2) * EMBED + ko + ld_ck2 * 8); \
    } while (0)

    QK_LOAD(0, 0); cp_commit();
    QK_LOAD(1, 1); cp_commit();

    for (int kb = 0; kb < NCH; ++kb) {
        if (kb < NCH - 2) cp_wait<1>(); else cp_wait<0>();
        __syncthreads();
        if (kb + 2 < NCH) { QK_LOAD((kb + 2) % 3, kb + 2); cp_commit(); }

        const uint32_t base = sb + (kb % 3) * QK_STAGE;
#pragma unroll
        for (int ks = 0; ks < 2; ks++) {
            uint32_t af[2][4];
#pragma unroll
            for (int mt = 0; mt < 2; mt++) {
                int row = wm * 32 + mt * 16 + a_mrow;
                ldsm_x4(af[mt][0], af[mt][1], af[mt][2], af[mt][3],
                        base + row * 64 + SWZ(row, ks * 32 + a_kch * 16));
            }
#pragma unroll
            for (int p = 0; p < 4; p++) {
                int row = wn * 64 + p * 16 + b_row8;
                uint32_t b0, b1, b2, b3;
                ldsm_x4(b0, b1, b2, b3, base + 8192 + row * 64 + SWZ(row, ks * 32 + b_kch * 16));
#pragma unroll
                for (int mt = 0; mt < 2; mt++) {
                    mma_bf16(acc[mt][2 * p],     af[mt], b0, b1);
                    mma_bf16(acc[mt][2 * p + 1], af[mt], b2, b3);
                }
            }
        }
        __syncthreads();
    }

    const int g = lane >> 2, t4 = lane & 3;
    float rmax[4] = {-3.4e38f, -3.4e38f, -3.4e38f, -3.4e38f};
#pragma unroll
    for (int mt = 0; mt < 2; mt++) {
        const int r0 = bm + wm * 32 + mt * 16 + g;
#pragma unroll
        for (int nt = 0; nt < 8; nt++) {
            const int cc = bn + wn * 64 + nt * 8 + t4 * 2;
            float v0 = acc[mt][nt][0] * 0.03125f;
            float v1 = acc[mt][nt][1] * 0.03125f;
            float v2 = acc[mt][nt][2] * 0.03125f;
            float v3 = acc[mt][nt][3] * 0.03125f;
            *(__nv_bfloat162*)(S + (size_t)r0 * NTOK + cc)       = __floats2bfloat162_rn(v0, v1);
            *(__nv_bfloat162*)(S + (size_t)(r0 + 8) * NTOK + cc) = __floats2bfloat162_rn(v2, v3);
            rmax[mt * 2 + 0] = fmaxf(rmax[mt * 2 + 0], fmaxf(v0, v1));
            rmax[mt * 2 + 1] = fmaxf(rmax[mt * 2 + 1], fmaxf(v2, v3));
        }
    }
#pragma unroll
    for (int s = 0; s < 4; s++) {
        rmax[s] = fmaxf(rmax[s], __shfl_xor_sync(0xffffffff, rmax[s], 1));
        rmax[s] = fmaxf(rmax[s], __shfl_xor_sync(0xffffffff, rmax[s], 2));
    }
    if (t4 == 0) {
#pragma unroll
        for (int mt = 0; mt < 2; mt++) {
            atomicMax(&rowmax[bm + wm * 32 + mt * 16 + g],     enc_ord(rmax[mt * 2 + 0]));
            atomicMax(&rowmax[bm + wm * 32 + mt * 16 + g + 8], enc_ord(rmax[mt * 2 + 1]));
        }
    }
}

// ---------------- select finalists + exact rescore + softmax + gather ----------------
__global__ __launch_bounds__(256)
void select_rescore_gather(const __nv_bfloat16* __restrict__ S, const unsigned* __restrict__ rowmax,
                           const float* __restrict__ Q, const float* __restrict__ K,
                           const float* __restrict__ X, float* __restrict__ O)
{
    __shared__ float red[256];
    __shared__ int   s_cnt;
    __shared__ int   s_idx[CAP];
    __shared__ float s_lg[CAP];
    __shared__ float ws[NTOK];   // fallback-only scratch

    const int row = blockIdx.x;
    const int tid = threadIdx.x;
    const float thr = dec_ord(rowmax[row]) - WINDOW;
    const uint4* p = (const uint4*)(S + (size_t)row * NTOK);

    if (tid == 0) s_cnt = 0;
    __syncthreads();

#pragma unroll
    for (int i = 0; i < 4; i++) {
        uint4 u = p[tid + i * 256];
        float f[8];
        __nv_bfloat162 h;
        h = *(__nv_bfloat162*)&u.x; f[0] = __low2float(h); f[1] = __high2float(h);
        h = *(__nv_bfloat162*)&u.y; f[2] = __low2float(h); f[3] = __high2float(h);
        h = *(__nv_bfloat162*)&u.z; f[4] = __low2float(h); f[5] = __high2float(h);
        h = *(__nv_bfloat162*)&u.w; f[6] = __low2float(h); f[7] = __high2float(h);
#pragma unroll
        for (int c = 0; c < 8; c++) {
            if (f[c] > thr) {
                int k = atomicAdd(&s_cnt, 1);
                if (k < CAP) s_idx[k] = (tid + i * 256) * 8 + c;
            }
        }
    }
    __syncthreads();
    const int cnt = s_cnt;
    const int col = tid * 4;

    if (cnt <= CAP) {
        const float4 q4 = *(const float4*)(Q + (size_t)row * EMBED + col);
        for (int t = 0; t < cnt; t++) {
            const float4 k4 = *(const float4*)(K + (size_t)s_idx[t] * EMBED + col);
            red[tid] = q4.x * k4.x + q4.y * k4.y + q4.z * k4.z + q4.w * k4.w;
            __syncthreads();
            for (int s = 128; s > 0; s >>= 1) {
                if (tid < s) red[tid] += red[tid + s];
                __syncthreads();
            }
            if (tid == 0) s_lg[t] = red[0] * 0.03125f;
            __syncthreads();
        }
        float mx = -3.402823466e+38f;
        for (int t = 0; t < cnt; t++) mx = fmaxf(mx, s_lg[t]);
        float sum = 0.f;
        for (int t = 0; t < cnt; t++) sum += expf(s_lg[t] - mx);
        const float inv = 1.f / sum;

        float a0 = 0.f, a1 = 0.f, a2 = 0.f, a3 = 0.f;
        for (int t = 0; t < cnt; t++) {
            const float w = expf(s_lg[t] - mx) * inv;
            const float4 x = *(const float4*)(X + (size_t)s_idx[t] * EMBED + col);
            a0 = fmaf(w, x.x, a0); a1 = fmaf(w, x.y, a1);
            a2 = fmaf(w, x.z, a2); a3 = fmaf(w, x.w, a3);
        }
        *(float4*)(O + (size_t)row * EMBED + col) = make_float4(a0, a1, a2, a3);
    } else {
        const float* qr = Q + (size_t)row * EMBED;
        for (int j = tid; j < NTOK; j += 256) {
            const float* kr = K + (size_t)j * EMBED;
            float d = 0.f;
            for (int e = 0; e < EMBED; e += 4) {
                float4 a = *(const float4*)(qr + e);
                float4 b = *(const float4*)(kr + e);
                d += a.x * b.x + a.y * b.y + a.z * b.z + a.w * b.w;
            }
            ws[j] = d * 0.03125f;
        }
        __syncthreads();
        float mx = -3.402823466e+38f;
        for (int j = tid; j < NTOK; j += 256) mx = fmaxf(mx, ws[j]);
        red[tid] = mx; __syncthreads();
        for (int s = 128; s > 0; s >>= 1) {
            if (tid < s) red[tid] = fmaxf(red[tid], red[tid + s]);
            __syncthreads();
        }
        mx = red[0]; __syncthreads();
        float sum = 0.f;
        for (int j = tid; j < NTOK; j += 256) sum += expf(ws[j] - mx);
        red[tid] = sum; __syncthreads();
        for (int s = 128; s > 0; s >>= 1) {
            if (tid < s) red[tid] += red[tid + s];
            __syncthreads();
        }
        const float inv = 1.f / red[0];
        float a0 = 0.f, a1 = 0.f, a2 = 0.f, a3 = 0.f;
        for (int j = 0; j < NTOK; j++) {
            const float w = expf(ws[j] - mx) * inv;
            const float4 x = *(const float4*)(X + (size_t)j * EMBED + col);
            a0 = fmaf(w, x.x, a0); a1 = fmaf(w, x.y, a1);
            a2 = fmaf(w, x.z, a2); a3 = fmaf(w, x.w, a3);
        }
        *(float4*)(O + (size_t)row * EMBED + col) = make_float4(a0, a1, a2, a3);
    }
}

// ---------------- launch ----------------
extern "C" void kernel_launch(void* const* d_in, const int* in_sizes, int n_in,
                              void* d_out, int out_size)
{
    const float* Wr = (const float*)d_in[0];
    const float* We = (const float*)d_in[1];
    const float* X  = (const float*)d_in[2];
    float* out = (float*)d_out;

    float *Qp, *Kp;
    __nv_bfloat16 *Xhi, *Xlo, *Wrhi, *Wrlo, *Wehi, *Welo, *Qbp, *Kbp, *Sp;
    unsigned* rmx;
    cudaGetSymbolAddress((void**)&Qp,   g_Q);
    cudaGetSymbolAddress((void**)&Kp,   g_K);
    cudaGetSymbolAddress((void**)&Xhi,  g_Xhi);
    cudaGetSymbolAddress((void**)&Xlo,  g_Xlo);
    cudaGetSymbolAddress((void**)&Wrhi, g_Wrhi);
    cudaGetSymbolAddress((void**)&Wrlo, g_Wrlo);
    cudaGetSymbolAddress((void**)&Wehi, g_Wehi);
    cudaGetSymbolAddress((void**)&Welo, g_Welo);
    cudaGetSymbolAddress((void**)&Qbp,  g_Qb);
    cudaGetSymbolAddress((void**)&Kbp,  g_Kb);
    cudaGetSymbolAddress((void**)&Sp,   g_S);
    cudaGetSymbolAddress((void**)&rmx,  g_rowmax);

    // unconditional (no static guards allowed); host-side, capture-time only
    cudaFuncSetAttribute(xw_bf16x3, cudaFuncAttributeMaxDynamicSharedMemorySize, 3 * XW_STAGE);

    dim3 blk(256);
    conv_split_x<<<(NTOK * EMBED) / (256 * 4), blk>>>(X, Xhi, Xlo);
    conv_split_wT<<<dim3(32, 32), blk>>>(Wr, Wrhi, Wrlo);
    conv_split_wT<<<dim3(32, 32), blk>>>(We, Wehi, Welo);
    init_rowmax<<<NTOK / 256, blk>>>(rmx);
    // Q = X@Wr, K = X@We (bf16x3, fp32-quality) + bf16 copies
    xw_bf16x3<<<dim3(EMBED / 128, NTOK / 128), blk, 3 * XW_STAGE>>>(Xhi, Xlo, Wrhi, Wrlo, Qp, Qbp);
    xw_bf16x3<<<dim3(EMBED / 128, NTOK / 128), blk, 3 * XW_STAGE>>>(Xhi, Xlo, Wehi, Welo, Kp, Kbp);
    // approx logits + rowmax
    qk_hmma<<<dim3(NTOK / 128, NTOK / 128), blk>>>(Qbp, Kbp, Sp, rmx);
    // finalists: exact rescore + softmax + gather
    select_rescore_gather<<<NTOK, blk>>>(Sp, rmx, Qp, Kp, X, out);
}